// round 7
// baseline (speedup 1.0000x reference)
#include <cuda_runtime.h>
#include <stdint.h>

// adjacency_full[i, neighbor_indices[i, j]] = adjacency_values[i, j]
// N = 8192, K = 64. Output: N*N fp32 (256 MB).
//
// Persistent-CTA variant: one resident wave (1184 CTAs = 148 SMs x 8),
// each CTA processes ~7 rows via grid-stride. The (col,val) pairs for the
// NEXT row are prefetched while the CURRENT row's zeros stream out, so the
// store pipe never stalls on loads and there are no wave transitions.
//   per row:  fill 32KB with STG.128 (.cs evict-first)  ->  __syncthreads
//             -> 64 register-resident value stores (L2-hot).

#define N_PATCHES 8192
#define K_NEIGH   64
#define THREADS   256
#define CHUNKS    (N_PATCHES / 4)        // 2048 float4 per row
#define PER_THR   (CHUNKS / THREADS)     // 8 chunks per thread
#define GRID      1184                   // 148 SMs * 8 CTAs (one wave)

__global__ __launch_bounds__(THREADS)
void persistent_fill_scatter_kernel(const float* __restrict__ vals,
                                    const int*   __restrict__ idx,
                                    float* __restrict__ out)
{
    const int tid = threadIdx.x;
    const float4 z4 = make_float4(0.f, 0.f, 0.f, 0.f);

    int r = blockIdx.x;

    // Prefetch first row's scatter operands.
    int   c = 0;
    float v = 0.f;
    if (tid < K_NEIGH && r < N_PATCHES) {
        int t = r * K_NEIGH + tid;
        c = idx[t];
        v = vals[t];
    }

    for (; r < N_PATCHES; ) {
        float* rowp = out + (size_t)r * N_PATCHES;
        float4* out4 = reinterpret_cast<float4*>(rowp);

        const int rn = r + GRID;  // next row this CTA will handle

        // Kick off next row's operand loads (latency hidden under the fill).
        int   cn = 0;
        float vn = 0.f;
        if (tid < K_NEIGH && rn < N_PATCHES) {
            int t = rn * K_NEIGH + tid;
            cn = idx[t];
            vn = vals[t];
        }

        // Fill current row with zeros: 8 independent STG.128, evict-first.
        #pragma unroll
        for (int j = 0; j < PER_THR; j++)
            __stcs(&out4[tid + j * THREADS], z4);

        // Zero stores happen-before value stores (CTA scope).
        __syncthreads();

        // Scatter current row's 64 values (operands already in registers).
        if (tid < K_NEIGH)
            rowp[c] = v;

        // Rotate pipeline.
        c = cn;
        v = vn;
        r = rn;
    }
}

extern "C" void kernel_launch(void* const* d_in, const int* in_sizes, int n_in,
                              void* d_out, int out_size)
{
    const float* vals = (const float*)d_in[0];   // [N, K] float32
    const int*   idx  = (const int*)  d_in[1];   // [N, K] int32
    float* out = (float*)d_out;                  // [N, N] float32

    persistent_fill_scatter_kernel<<<GRID, THREADS, 0, 0>>>(vals, idx, out);
}

// round 8
// speedup vs baseline: 1.0740x; 1.0740x over previous
#include <cuda_runtime.h>
#include <stdint.h>

// adjacency_full[i, neighbor_indices[i, j]] = adjacency_values[i, j]
// N = 8192, K = 64. Output: N*N fp32 (256 MB).
//
// R4 structure (best known): one CTA per row.
//   1) stream the row's 8192 zeros with 256-bit stores (st.global.v8.f32,
//      sm_100a+): 4 STG.256 per thread, 1KB contiguous per warp-instruction.
//   2) __syncthreads()  — zero stores happen-before value stores.
//   3) threads 0..63 scatter the row's 64 values (L2-hot lines).

#define N_PATCHES 8192
#define K_NEIGH   64
#define THREADS   256
#define CHUNKS8   (N_PATCHES / 8)        // 1024 v8 (32B) chunks per row
#define PER_THR   (CHUNKS8 / THREADS)    // 4 v8 chunks per thread

__device__ __forceinline__ void stg256_zero(float* p)
{
    asm volatile(
        "st.global.v8.f32 [%0], {%1, %1, %1, %1, %1, %1, %1, %1};"
        :: "l"(p), "f"(0.0f) : "memory");
}

__global__ __launch_bounds__(THREADS)
void fused_v8_kernel(const float* __restrict__ vals,
                     const int*   __restrict__ idx,
                     float* __restrict__ out)
{
    const int r   = blockIdx.x;
    const int tid = threadIdx.x;

    float* rowp = out + (size_t)r * N_PATCHES;

    // Phase 1: zero fill with 256-bit stores (32B per thread-instr, coalesced).
    #pragma unroll
    for (int j = 0; j < PER_THR; j++)
        stg256_zero(rowp + (tid + j * THREADS) * 8);

    // All zero-stores of this CTA happen-before the value stores.
    __syncthreads();

    // Phase 2: scatter the 64 values (lines still hot in L2).
    if (tid < K_NEIGH) {
        int t = r * K_NEIGH + tid;
        int c = idx[t];                  // coalesced read
        rowp[c] = vals[t];               // 4B store into hot L2 line
    }
}

extern "C" void kernel_launch(void* const* d_in, const int* in_sizes, int n_in,
                              void* d_out, int out_size)
{
    const float* vals = (const float*)d_in[0];   // [N, K] float32
    const int*   idx  = (const int*)  d_in[1];   // [N, K] int32
    float* out = (float*)d_out;                  // [N, N] float32

    fused_v8_kernel<<<N_PATCHES, THREADS, 0, 0>>>(vals, idx, out);
}

// round 9
// speedup vs baseline: 1.1309x; 1.0529x over previous
#include <cuda_runtime.h>
#include <stdint.h>

// adjacency_full[i, neighbor_indices[i, j]] = adjacency_values[i, j]
// N = 8192, K = 64. Output: N*N fp32 (256 MB).
//
// TMA bulk-store probe: one CTA per row. Build the finished 32KB row in
// shared memory (STS zero-fill + 64-value scatter), then stream it to GMEM
// with a single cp.async.bulk (shared::cta -> global) issued by one thread.
// This bypasses the LSU/L1 store path entirely; the async proxy drains the
// row while other CTAs on the SM build theirs.

#define N_PATCHES 8192
#define K_NEIGH   64
#define THREADS   256
#define ROW_BYTES (N_PATCHES * 4)        // 32 KB
#define ROW_VEC4  (N_PATCHES / 4)        // 2048 float4

__global__ __launch_bounds__(THREADS)
void tma_row_kernel(const float* __restrict__ vals,
                    const int*   __restrict__ idx,
                    float* __restrict__ out)
{
    __shared__ __align__(128) float row[N_PATCHES];   // 32 KB
    const int r   = blockIdx.x;
    const int tid = threadIdx.x;

    // Phase 0: prefetch scatter operands (hidden under the smem zero-fill).
    int   c = 0;
    float v = 0.f;
    if (tid < K_NEIGH) {
        int t = r * K_NEIGH + tid;
        c = idx[t];
        v = vals[t];
    }

    // Phase 1: zero the row in shared memory (vectorized STS).
    float4* row4 = reinterpret_cast<float4*>(row);
    const float4 z4 = make_float4(0.f, 0.f, 0.f, 0.f);
    #pragma unroll
    for (int j = 0; j < ROW_VEC4 / THREADS; j++)
        row4[tid + j * THREADS] = z4;
    __syncthreads();

    // Phase 2: scatter the 64 values into the smem row.
    if (tid < K_NEIGH)
        row[c] = v;
    __syncthreads();

    // Phase 3: make generic-proxy STS visible to the async proxy, then
    // issue one 32KB bulk store smem -> gmem from a single thread.
    asm volatile("fence.proxy.async.shared::cta;" ::: "memory");
    if (tid == 0) {
        uint32_t saddr;
        asm("{ .reg .u64 t; cvta.to.shared.u64 t, %1; cvt.u32.u64 %0, t; }"
            : "=r"(saddr) : "l"(row));
        float* dst = out + (size_t)r * N_PATCHES;
        asm volatile(
            "cp.async.bulk.global.shared::cta.bulk_group [%0], [%1], %2;"
            :: "l"(dst), "r"(saddr), "r"(ROW_BYTES) : "memory");
        asm volatile("cp.async.bulk.commit_group;" ::: "memory");
        // Keep smem alive until the bulk store has read it / completed.
        asm volatile("cp.async.bulk.wait_group 0;" ::: "memory");
    }
}

extern "C" void kernel_launch(void* const* d_in, const int* in_sizes, int n_in,
                              void* d_out, int out_size)
{
    const float* vals = (const float*)d_in[0];   // [N, K] float32
    const int*   idx  = (const int*)  d_in[1];   // [N, K] int32
    float* out = (float*)d_out;                  // [N, N] float32

    tma_row_kernel<<<N_PATCHES, THREADS, 0, 0>>>(vals, idx, out);
}